// round 17
// baseline (speedup 1.0000x reference)
#include <cuda_runtime.h>
#include <cuda_bf16.h>
#include <cuda_fp16.h>
#include <stdint.h>

// ---------------- problem constants ----------------
#define NATOMS   16384
#define NSEL     4096
#define NODE_F   8
#define HID      128
#define HEADS    8
#define DH       16
#define OUTD     256
#define NLIG     32
#define NBINS    65536
#define NCHUNK   1024     // coarse chunks of 64 fine bins
#define CDIM     32       // spatial cells per axis (cell size 3.0)
#define NCELLS   (CDIM * CDIM * CDIM)   // 32768

#define GRID_ALL 576      // 64 atom-blocks x 9 neighbor splits; co-resident on 148 SMs

#define TQ 128     // queries per attention block (32 per warp-quad)
#define TK 128     // keys per smem tile
#define KPAD 24    // smem row stride in fp16 (48B: 16B-aligned, ldmatrix conflict-free)
#define TILEB (TK * KPAD * 2)   // 6144 bytes per tile array

// softmax range shift (log2 units): p = 2^(S - SHIFT); cancels exactly in o/l.
#define SM_SHIFT 8.0f

typedef unsigned long long ull;

// ---------------- helpers ----------------
__device__ __forceinline__ unsigned scvt(const void* p) {
    return (unsigned)__cvta_generic_to_shared(p);
}
__device__ __forceinline__ void ldm_x4(unsigned* r, unsigned a) {
    asm volatile("ldmatrix.sync.aligned.m8n8.x4.shared.b16 {%0,%1,%2,%3}, [%4];"
        : "=r"(r[0]), "=r"(r[1]), "=r"(r[2]), "=r"(r[3]) : "r"(a));
}
__device__ __forceinline__ void ldm_x4t(unsigned* r, unsigned a) {
    asm volatile("ldmatrix.sync.aligned.m8n8.x4.trans.shared.b16 {%0,%1,%2,%3}, [%4];"
        : "=r"(r[0]), "=r"(r[1]), "=r"(r[2]), "=r"(r[3]) : "r"(a));
}
__device__ __forceinline__ void mma16816f(float* d, const unsigned* a, const unsigned* b) {
    asm volatile(
        "mma.sync.aligned.m16n8k16.row.col.f32.f16.f16.f32 "
        "{%0,%1,%2,%3}, {%4,%5,%6,%7}, {%8,%9}, {%0,%1,%2,%3};"
        : "+f"(d[0]), "+f"(d[1]), "+f"(d[2]), "+f"(d[3])
        : "r"(a[0]), "r"(a[1]), "r"(a[2]), "r"(a[3]), "r"(b[0]), "r"(b[1]));
}
__device__ __forceinline__ unsigned cvt_f16x2(float lo, float hi) {
    unsigned r;
    asm("cvt.rn.satfinite.f16x2.f32 %0, %1, %2;" : "=r"(r) : "f"(hi), "f"(lo));
    return r;
}
__device__ __forceinline__ unsigned h2ex2(unsigned x) {
    unsigned r; asm("ex2.approx.f16x2 %0, %1;" : "=r"(r) : "r"(x)); return r;
}
__device__ __forceinline__ void half_bar(int id) {
    asm volatile("bar.sync %0, %1;" :: "r"(id), "r"(128) : "memory");
}

// ---------------- scratch (static device memory; no allocation) ----------------
__device__ unsigned g_barctr;          // monotonic global-barrier counter (never reset)
__device__ float    g_sq[NATOMS];
__device__ float    g_s0[NATOMS];
__device__ int      g_cnt[NATOMS];
__device__ int      g_cell[NATOMS];
__device__ int      g_cellcnt[NCELLS];
__device__ int      g_cellstart[NCELLS + 1];
__device__ int      g_cellptr[NCELLS];
__device__ __align__(16) float4 g_cellpos[NATOMS];   // (x, y, z, -0.5*sq)
__device__ unsigned g_keys[NATOMS];
__device__ unsigned g_hist[NBINS];
__device__ unsigned g_chist[NCHUNK];
__device__ int      g_H;
__device__ int      g_r;
__device__ int      g_m;
__device__ int      g_done;
__device__ ull      g_bbuf[NATOMS];
__device__ int      g_sel[NATOMS];
__device__ int      g_idx[NSEL];
__device__ __align__(16) __half g_qf[NSEL * HID];   // q * scale*log2e (fp16)
__device__ __align__(16) __half g_kf[NSEL * HID];   // k (fp16)
__device__ __align__(16) __half g_vf[NSEL * HID];   // V (fp16)
__device__ __align__(16) float g_av[NSEL * HID];
__device__ float    g_mav[HID];

// ---------------- software global barrier (all GRID_ALL blocks co-resident) ----------------
// Monotonic counter: each barrier waits for the next multiple of GRID_ALL above
// its own arrival. Consumes exactly GRID_ALL increments per barrier -> graph
// replays stay consistent with no reset.
__device__ __forceinline__ void gbar() {
    __syncthreads();
    if (threadIdx.x == 0) {
        __threadfence();
        unsigned old = atomicAdd(&g_barctr, 1u);
        unsigned target = (old / GRID_ALL + 1u) * GRID_ALL;
        unsigned v;
        do {
            asm volatile("ld.volatile.global.u32 %0, [%1];" : "=r"(v) : "l"(&g_barctr) : "memory");
            if (v < target) __nanosleep(64);
        } while (v < target);
    }
    __syncthreads();
}

// ---------------- merged selection pipeline: ONE kernel, 10 phases ----------------
// All phase bodies are verbatim from the proven R16 kernels; only the
// launch packaging changed (barriers instead of kernel boundaries).
__global__ __launch_bounds__(256) void k_all(const float* __restrict__ lig,
                                             const float* __restrict__ pos) {
    __shared__ float c3[3];
    __shared__ int wsum[8];
    __shared__ int wpre[8];
    __shared__ unsigned csum[NCHUNK];
    __shared__ unsigned hs64[64];
    __shared__ int s_chunk;
    __shared__ unsigned s_above;
    __shared__ int sc[256];
    __shared__ int s_off;

    int t = threadIdx.x, b = blockIdx.x;
    int gtid = b * 256 + t;
    int lane = t & 31, wid = t >> 5;

    // ---- phase 0: ligand center (per-block) + zero + per-atom base ----
    if (t < 32) {
        float x = lig[t * 3 + 0], y = lig[t * 3 + 1], z = lig[t * 3 + 2];
        #pragma unroll
        for (int o = 16; o > 0; o >>= 1) {
            x += __shfl_down_sync(0xFFFFFFFFu, x, o);
            y += __shfl_down_sync(0xFFFFFFFFu, y, o);
            z += __shfl_down_sync(0xFFFFFFFFu, z, o);
        }
        if (t == 0) {
            c3[0] = x * (1.0f / NLIG);
            c3[1] = y * (1.0f / NLIG);
            c3[2] = z * (1.0f / NLIG);
        }
    }
    __syncthreads();
    if (gtid < NBINS) g_hist[gtid] = 0;
    if (gtid < NCHUNK) g_chist[gtid] = 0;
    if (gtid < NCELLS) g_cellcnt[gtid] = 0;
    if (gtid == 0) { g_m = 0; g_done = 0; }
    if (gtid < NATOMS) {
        g_cnt[gtid] = 0;
        float x = pos[gtid * 3 + 0], y = pos[gtid * 3 + 1], z = pos[gtid * 3 + 2];
        g_sq[gtid] = fmaf(z, z, fmaf(y, y, x * x));
        float dx = x - c3[0], dy = y - c3[1], dz = z - c3[2];
        float d = sqrtf(fmaf(dz, dz, fmaf(dy, dy, dx * dx)));
        g_s0[gtid] = 1.0f / (1.0f + d / 5.0f);
    }
    gbar();

    // ---- phase 1: assign cells + count ----
    if (gtid < NATOMS) {
        float x = pos[gtid * 3 + 0], y = pos[gtid * 3 + 1], z = pos[gtid * 3 + 2];
        int cx = min(max((int)floorf(x * (1.0f / 3.0f)) + 16, 0), CDIM - 1);
        int cy = min(max((int)floorf(y * (1.0f / 3.0f)) + 16, 0), CDIM - 1);
        int cz = min(max((int)floorf(z * (1.0f / 3.0f)) + 16, 0), CDIM - 1);
        int cell = (cz * CDIM + cy) * CDIM + cx;
        g_cell[gtid] = cell;
        atomicAdd(&g_cellcnt[cell], 1);
    }
    gbar();

    // ---- phase 2: cell starts (blocks < 128; shuffle scans) ----
    if (b < 128) {
        int s = 0;
        for (int j = t; j < b * 256; j += 256) s += g_cellcnt[j];
        #pragma unroll
        for (int o = 16; o > 0; o >>= 1) s += __shfl_down_sync(0xFFFFFFFFu, s, o);
        if (lane == 0) wsum[wid] = s;
        __syncthreads();
        int soff = 0;
        {
            int v = (lane < 8) ? wsum[lane] : 0;
            #pragma unroll
            for (int o = 4; o > 0; o >>= 1) v += __shfl_down_sync(0xFFFFFFFFu, v, o);
            soff = __shfl_sync(0xFFFFFFFFu, v, 0);
        }
        int c = b * 256 + t;
        int cnt = g_cellcnt[c];
        int inc = cnt;
        #pragma unroll
        for (int o = 1; o < 32; o <<= 1) {
            int v = __shfl_up_sync(0xFFFFFFFFu, inc, o);
            if (lane >= o) inc += v;
        }
        if (lane == 31) wpre[wid] = inc;
        __syncthreads();
        int wbase = 0;
        #pragma unroll
        for (int w = 0; w < 8; w++) wbase += (w < wid) ? wpre[w] : 0;
        int start = soff + wbase + inc - cnt;
        g_cellstart[c] = start;
        g_cellptr[c]   = start;
        if (b == 0 && t == 0) g_cellstart[NCELLS] = NATOMS;
    }
    gbar();

    // ---- phase 3: scatter atoms into cell-sorted packed array ----
    if (gtid < NATOMS) {
        int slot = atomicAdd(&g_cellptr[g_cell[gtid]], 1);
        g_cellpos[slot] = make_float4(pos[gtid * 3 + 0], pos[gtid * 3 + 1], pos[gtid * 3 + 2],
                                      -0.5f * g_sq[gtid]);
    }
    gbar();

    // ---- phase 4: neighbor counting (s = b/64 covers the 9 (dy,dz) rows) ----
    {
        int s = b >> 6;                       // 0..8
        int i = (b & 63) * 256 + t;
        int dy = s % 3 - 1, dz = s / 3 - 1;
        float px = pos[i * 3 + 0], py = pos[i * 3 + 1], pz = pos[i * 3 + 2];
        float ci = 4.5f - 0.5f * g_sq[i];
        int cell = g_cell[i];
        int cx = cell % CDIM;
        int cy = (cell / CDIM) % CDIM;
        int cz = cell / (CDIM * CDIM);
        int ny = cy + dy, nz = cz + dz;
        int cnt = 0;
        if (ny >= 0 && ny < CDIM && nz >= 0 && nz < CDIM) {
            int rowbase = (nz * CDIM + ny) * CDIM;
            int lo = rowbase + max(cx - 1, 0);
            int hi = rowbase + min(cx + 1, CDIM - 1);
            int a = g_cellstart[lo];
            int e = g_cellstart[hi + 1];
            #pragma unroll 4
            for (int j = a; j < e; j++) {
                float4 q = g_cellpos[j];
                float v = fmaf(px, q.x, fmaf(py, q.y, fmaf(pz, q.z, q.w + ci)));
                cnt += (v > 0.0f);
            }
        }
        atomicAdd(&g_cnt[i], cnt);
    }
    gbar();

    // ---- phase 5: scores -> keys + histograms ----
    if (gtid < NATOMS) {
        float surface = 1.0f / (float)g_cnt[gtid];
        float s = g_s0[gtid] + 0.5f * surface;
        unsigned key = __float_as_uint(s);
        g_keys[gtid] = key;
        atomicAdd(&g_hist[key >> 16], 1u);
        atomicAdd(&g_chist[key >> 22], 1u);
    }
    gbar();

    // ---- phase 6: threshold bin (block 0; 256 threads, 4 chunks each) ----
    if (b == 0) {
        for (int j = t; j < NCHUNK; j += 256) csum[j] = g_chist[j];
        __syncthreads();
        for (int o = 1; o < NCHUNK; o <<= 1) {
            unsigned v[4];
            #pragma unroll
            for (int k = 0; k < 4; k++) {
                int idx = t + k * 256;
                v[k] = (idx + o < NCHUNK) ? csum[idx + o] : 0u;
            }
            __syncthreads();
            #pragma unroll
            for (int k = 0; k < 4; k++) csum[t + k * 256] += v[k];
            __syncthreads();
        }
        #pragma unroll
        for (int k = 0; k < 4; k++) {
            int idx = t + k * 256;
            unsigned mine = csum[idx];
            unsigned nxt = (idx + 1 < NCHUNK) ? csum[idx + 1] : 0u;
            if (mine >= (unsigned)NSEL && nxt < (unsigned)NSEL) { s_chunk = idx; s_above = nxt; }
        }
        __syncthreads();
        int chunk = s_chunk;
        unsigned above = s_above;
        if (t < 64) hs64[t] = g_hist[chunk * 64 + t];
        __syncthreads();
        for (int o = 1; o < 64; o <<= 1) {
            unsigned v = (t < 64 && t + o < 64) ? hs64[t + o] : 0u;
            __syncthreads();
            if (t < 64) hs64[t] += v;
            __syncthreads();
        }
        if (t < 64) {
            unsigned mine = above + hs64[t];
            unsigned nxt  = above + ((t + 1 < 64) ? hs64[t + 1] : 0u);
            if (mine >= (unsigned)NSEL && nxt < (unsigned)NSEL) {
                g_H = chunk * 64 + t;
                g_r = (int)((unsigned)NSEL - nxt);
            }
        }
    }
    gbar();

    // ---- phase 7: boundary-bin elements ----
    if (gtid < NATOMS) {
        unsigned key = g_keys[gtid];
        if ((int)(key >> 16) == g_H) {
            int p = atomicAdd(&g_m, 1);
            g_bbuf[p] = ((ull)key << 32) | (ull)(0xFFFFFFFFu - (unsigned)gtid);
        }
    }
    gbar();

    // ---- phase 8: selection flags ----
    if (gtid < NATOMS) {
        unsigned key = g_keys[gtid];
        int hi = (int)(key >> 16);
        int s = 0;
        if (hi > g_H) s = 1;
        else if (hi == g_H) {
            ull mine = ((ull)key << 32) | (ull)(0xFFFFFFFFu - (unsigned)gtid);
            int m = g_m, cnt = 0, r = g_r;
            for (int j = 0; j < m; j++) cnt += (g_bbuf[j] > mine);
            if (cnt < r) s = 1;
        }
        g_sel[gtid] = s;
    }
    gbar();

    // ---- phase 9: single-pass deterministic compaction (blocks < 64) ----
    if (b < 64) {
        int pre = b * 256;
        int s = 0;
        for (int j = t; j < pre; j += 256) s += g_sel[j];
        sc[t] = s;
        __syncthreads();
        for (int o = 128; o > 0; o >>= 1) {
            if (t < o) sc[t] += sc[t + o];
            __syncthreads();
        }
        if (t == 0) s_off = sc[0];
        __syncthreads();
        int i = pre + t;
        int f = g_sel[i];
        sc[t] = f;
        __syncthreads();
        for (int o = 1; o < 256; o <<= 1) {
            int v = (t >= o) ? sc[t - o] : 0;
            __syncthreads();
            sc[t] += v;
            __syncthreads();
        }
        if (f) g_idx[s_off + sc[t] - 1] = i;
    }
}

// ---------------- gather + embed + QKV (fp16 outputs) — unchanged (proven R16) ----------------
__global__ __launch_bounds__(256) void k_qkv(
    const float* __restrict__ x,
    const float* __restrict__ Wn, const float* __restrict__ bn,
    const float* __restrict__ Wq, const float* __restrict__ bq,
    const float* __restrict__ Wk, const float* __restrict__ bk,
    const float* __restrict__ Wv, const float* __restrict__ bv)
{
    __shared__ float hs[16][HID];
    int t = threadIdx.x;
    int c = t & 127;
    int half = t >> 7;
    int r0 = blockIdx.x * 16;
    #pragma unroll
    for (int k = 0; k < 8; k++) {
        int rr = half * 8 + k;
        int row = g_idx[r0 + rr];
        const float* xr = x + row * NODE_F;
        float acc = bn[c];
        #pragma unroll
        for (int f = 0; f < NODE_F; f++) acc = fmaf(__ldg(xr + f), Wn[f * HID + c], acc);
        hs[rr][c] = acc;
    }
    __syncthreads();
    float aq[8], ak[8], av[8];
    #pragma unroll
    for (int rr = 0; rr < 8; rr++) { aq[rr] = bq[c]; ak[rr] = bk[c]; av[rr] = bv[c]; }
    for (int d = 0; d < HID; d++) {
        float wq = Wq[d * HID + c], wk = Wk[d * HID + c], wv = Wv[d * HID + c];
        #pragma unroll
        for (int rr = 0; rr < 8; rr++) {
            float h = hs[half * 8 + rr][d];
            aq[rr] = fmaf(h, wq, aq[rr]);
            ak[rr] = fmaf(h, wk, ak[rr]);
            av[rr] = fmaf(h, wv, av[rr]);
        }
    }
    const float cs = 0.25f * 1.4426950408889634f;
    #pragma unroll
    for (int rr = 0; rr < 8; rr++) {
        int o = (r0 + half * 8 + rr) * HID + c;
        g_qf[o] = __float2half_rn(aq[rr] * cs);
        g_kf[o] = __float2half_rn(ak[rr]);
        g_vf[o] = __float2half_rn(av[rr]);
    }
}

// ---------------- tensor-core attention, fp16, TQ=128, split-K x2 — unchanged (proven R16) ----------------
__global__ __launch_bounds__(256) void k_attn_tc() {
    __shared__ __align__(16) char sraw[4 * TILEB];   // 24KB

    int h    = blockIdx.y;
    int q0   = blockIdx.x * TQ;
    int tid  = threadIdx.x;
    int warp = tid >> 5;
    int lane = tid & 31;
    int qw   = warp & 3;
    int half = warp >> 2;
    int lt   = tid & 127;

    __half (*sK)[KPAD] = (__half (*)[KPAD])(sraw + half * 2 * TILEB + 0 * TILEB);
    __half (*sV)[KPAD] = (__half (*)[KPAD])(sraw + half * 2 * TILEB + 1 * TILEB);

    {
        __half (*qS)[KPAD] = (__half (*)[KPAD])(sraw);
        int row = tid >> 1, hf = tid & 1;
        *(uint4*)&qS[row][hf * 8] = *(const uint4*)(g_qf + (q0 + row) * HID + h * DH + hf * 8);
        __syncthreads();
    }
    unsigned a0[4], a1[4];
    {
        __half (*qS)[KPAD] = (__half (*)[KPAD])(sraw);
        int mrow = qw * 32 + ((lane >> 3) & 1) * 8 + (lane & 7);
        unsigned coff = (lane >> 4) * 16;
        ldm_x4(a0, scvt(&qS[mrow][0]) + coff);
        ldm_x4(a1, scvt(&qS[mrow + 16][0]) + coff);
    }
    __syncthreads();

    float o0[8], o1[8];
    #pragma unroll
    for (int i = 0; i < 8; i++) { o0[i] = 0.0f; o1[i] = 0.0f; }
    float L0[4], L1[4];
    #pragma unroll
    for (int i = 0; i < 4; i++) { L0[i] = 0.0f; L1[i] = 0.0f; }
    const unsigned ONES2 = 0x3C003C00u;
    unsigned bones[2] = {ONES2, ONES2};

    int krow = ((lane >> 4) & 1) * 8 + (lane & 7);
    unsigned kcoff = ((lane >> 3) & 1) * 16;
    int vrow = (lane & 7) + ((lane >> 3) & 1) * 8;
    unsigned vcoff = ((lane >> 4) & 1) * 16;
    int bar_id = 1 + half;

    for (int it = 0; it < 16; it++) {
        int kt = half * 16 + it;
        {
            int src = (kt * TK + lt) * HID + h * DH;
            const uint4* kf = (const uint4*)(g_kf + src);
            const uint4* vf = (const uint4*)(g_vf + src);
            *(uint4*)&sK[lt][0] = kf[0]; *(uint4*)&sK[lt][8] = kf[1];
            *(uint4*)&sV[lt][0] = vf[0]; *(uint4*)&sV[lt][8] = vf[1];
        }
        half_bar(bar_id);

        #pragma unroll
        for (int g16 = 0; g16 < TK / 16; g16++) {
            unsigned bk[4];
            ldm_x4(bk, scvt(&sK[g16 * 16 + krow][0]) + kcoff);
            float S0[8], S1[8];
            #pragma unroll
            for (int i = 0; i < 8; i++) { S0[i] = -SM_SHIFT; S1[i] = -SM_SHIFT; }
            mma16816f(S0,     a0, bk);
            mma16816f(S0 + 4, a0, bk + 2);
            mma16816f(S1,     a1, bk);
            mma16816f(S1 + 4, a1, bk + 2);

            unsigned pa0[4], pa1[4];
            pa0[0] = h2ex2(cvt_f16x2(S0[0], S0[1]));
            pa0[1] = h2ex2(cvt_f16x2(S0[2], S0[3]));
            pa0[2] = h2ex2(cvt_f16x2(S0[4], S0[5]));
            pa0[3] = h2ex2(cvt_f16x2(S0[6], S0[7]));
            pa1[0] = h2ex2(cvt_f16x2(S1[0], S1[1]));
            pa1[1] = h2ex2(cvt_f16x2(S1[2], S1[3]));
            pa1[2] = h2ex2(cvt_f16x2(S1[4], S1[5]));
            pa1[3] = h2ex2(cvt_f16x2(S1[6], S1[7]));

            mma16816f(L0, pa0, bones);
            mma16816f(L1, pa1, bones);

            unsigned bv[4];
            ldm_x4t(bv, scvt(&sV[g16 * 16 + vrow][0]) + vcoff);
            mma16816f(o0,     pa0, bv);
            mma16816f(o0 + 4, pa0, bv + 2);
            mma16816f(o1,     pa1, bv);
            mma16816f(o1 + 4, pa1, bv + 2);
        }
        half_bar(bar_id);
    }

    __syncthreads();
    float* sO = (float*)sraw;
    if (half == 1) {
        float* dst = sO + (qw * 32 + lane) * 20;
        #pragma unroll
        for (int i = 0; i < 8; i++) { dst[i] = o0[i]; dst[8 + i] = o1[i]; }
        dst[16] = L0[0]; dst[17] = L0[2]; dst[18] = L1[0]; dst[19] = L1[2];
    }
    __syncthreads();
    if (half == 1) return;

    float l0, l1, l2, l3;
    {
        const float* srcp = sO + (qw * 32 + lane) * 20;
        #pragma unroll
        for (int i = 0; i < 8; i++) { o0[i] += srcp[i]; o1[i] += srcp[8 + i]; }
        l0 = L0[0] + srcp[16];
        l1 = L0[2] + srcp[17];
        l2 = L1[0] + srcp[18];
        l3 = L1[2] + srcp[19];
    }
    float inv0 = 1.0f / l0, inv1 = 1.0f / l1, inv2 = 1.0f / l2, inv3 = 1.0f / l3;

    int r0c = lane >> 2;
    int cc  = (lane & 3) * 2;
    int row0 = q0 + qw * 32 + r0c;
    float* d0 = g_av + row0 * HID + h * DH;
    float* d1 = g_av + (row0 + 8) * HID + h * DH;
    float* d2 = g_av + (row0 + 16) * HID + h * DH;
    float* d3 = g_av + (row0 + 24) * HID + h * DH;
    d0[cc]     = o0[0] * inv0;  d0[cc + 1] = o0[1] * inv0;
    d1[cc]     = o0[2] * inv1;  d1[cc + 1] = o0[3] * inv1;
    d0[cc + 8] = o0[4] * inv0;  d0[cc + 9] = o0[5] * inv0;
    d1[cc + 8] = o0[6] * inv1;  d1[cc + 9] = o0[7] * inv1;
    d2[cc]     = o1[0] * inv2;  d2[cc + 1] = o1[1] * inv2;
    d3[cc]     = o1[2] * inv3;  d3[cc + 1] = o1[3] * inv3;
    d2[cc + 8] = o1[4] * inv2;  d2[cc + 9] = o1[5] * inv2;
    d3[cc + 8] = o1[6] * inv3;  d3[cc + 9] = o1[7] * inv3;
}

// ---------------- column mean + (last block) Wo/MLP head — unchanged ----------------
__global__ __launch_bounds__(256) void k_colsum_final(
    const float* __restrict__ Wo, const float* __restrict__ bo,
    const float* __restrict__ W1, const float* __restrict__ b1,
    const float* __restrict__ W2, const float* __restrict__ b2,
    float* __restrict__ out)
{
    __shared__ float sm[256];
    __shared__ int is_last;
    int col = blockIdx.x;
    int t = threadIdx.x;
    float s = 0.0f;
    for (int r = t; r < NSEL; r += 256) s += g_av[r * HID + col];
    sm[t] = s;
    __syncthreads();
    for (int o = 128; o > 0; o >>= 1) {
        if (t < o) sm[t] += sm[t + o];
        __syncthreads();
    }
    if (t == 0) {
        g_mav[col] = sm[0] * (1.0f / NSEL);
        __threadfence();
        is_last = (atomicAdd(&g_done, 1) == HID - 1);
    }
    __syncthreads();
    if (!is_last) return;

    __shared__ float mav[HID];
    __shared__ float pooled[HID];
    __shared__ float t1[OUTD];
    if (t < HID) mav[t] = g_mav[t];
    __syncthreads();
    if (t < HID) {
        float acc = bo[t];
        for (int d = 0; d < HID; d++) acc = fmaf(mav[d], Wo[d * HID + t], acc);
        pooled[t] = acc;
    }
    __syncthreads();
    {
        float acc = b1[t];
        for (int d = 0; d < HID; d++) acc = fmaf(pooled[d], W1[d * OUTD + t], acc);
        t1[t] = fmaxf(acc, 0.0f);
    }
    __syncthreads();
    {
        float acc = b2[t];
        for (int d = 0; d < OUTD; d++) acc = fmaf(t1[d], W2[d * OUTD + t], acc);
        out[t] = acc;
    }
}

// ---------------- launcher ----------------
extern "C" void kernel_launch(void* const* d_in, const int* in_sizes, int n_in,
                              void* d_out, int out_size)
{
    const float* x    = (const float*)d_in[0];
    const float* pos  = (const float*)d_in[1];
    const float* lig  = (const float*)d_in[2];
    const float* Wn   = (const float*)d_in[3];
    const float* bn   = (const float*)d_in[4];
    const float* Wq   = (const float*)d_in[5];
    const float* bq   = (const float*)d_in[6];
    const float* Wk   = (const float*)d_in[7];
    const float* bk   = (const float*)d_in[8];
    const float* Wv   = (const float*)d_in[9];
    const float* bv   = (const float*)d_in[10];
    const float* Wo   = (const float*)d_in[11];
    const float* bo   = (const float*)d_in[12];
    const float* W1   = (const float*)d_in[13];
    const float* b1   = (const float*)d_in[14];
    const float* W2   = (const float*)d_in[15];
    const float* b2   = (const float*)d_in[16];
    float* out = (float*)d_out;

    k_all<<<GRID_ALL, 256>>>(lig, pos);
    k_qkv<<<NSEL / 16, 256>>>(x, Wn, bn, Wq, bq, Wk, bk, Wv, bv);
    k_attn_tc<<<dim3(NSEL / TQ, HEADS), 256>>>();
    k_colsum_final<<<HID, 256>>>(Wo, bo, W1, b1, W2, b2, out);
}